// round 12
// baseline (speedup 1.0000x reference)
#include <cuda_runtime.h>

#define NB 8
#define NA 120000
#define NM 64
#define TPB 128
#define APT 2                       // anchors per thread
#define SPAN (APT * TPB)            // anchors per block = 256
#define GRIDX ((NA + SPAN - 1) / SPAN)
#define TOTAL_BLOCKS (GRIDX * NB)

#define NCELL_1D 64
#define NCELL (NCELL_1D * NCELL_1D)
#define CELL_SCALE (64.0f / 800.0f)   // field ~[0,800] -> 64 cells

__device__ float    g_cls[NB];
__device__ float    g_reg[NB];
__device__ int      g_pos[NB];
__device__ unsigned g_ctr;

__device__ int g_hist[NCELL];
__device__ int g_offs[NCELL];
__device__ int g_cur[NCELL];
__device__ int g_sidx[NA];

__device__ __forceinline__ int cell_of(const float4 A) {
    float cx = 0.5f * (A.x + A.z);
    float cy = 0.5f * (A.y + A.w);
    int ix = min(max((int)(cx * CELL_SCALE), 0), NCELL_1D - 1);
    int iy = min(max((int)(cy * CELL_SCALE), 0), NCELL_1D - 1);
    return iy * NCELL_1D + ix;
}

__global__ void k_zero() {
    int i = blockIdx.x * blockDim.x + threadIdx.x;
    if (i < NCELL) { g_hist[i] = 0; g_cur[i] = 0; }
}

__global__ void k_hist(const float* __restrict__ anc) {
    int a = blockIdx.x * blockDim.x + threadIdx.x;
    if (a < NA) atomicAdd(&g_hist[cell_of(__ldg((const float4*)anc + a))], 1);
}

__global__ void k_scan() {     // exclusive scan of g_hist (4096) -> g_offs
    __shared__ int warp_tot[32];
    int tid = threadIdx.x;     // 1024 threads, 4 cells each
    int base = tid * 4;
    int v0 = g_hist[base], v1 = g_hist[base + 1], v2 = g_hist[base + 2], v3 = g_hist[base + 3];
    int local = v0 + v1 + v2 + v3;
    int lane = tid & 31, wid = tid >> 5;
    int x = local;
    #pragma unroll
    for (int o = 1; o < 32; o <<= 1) { int y = __shfl_up_sync(~0u, x, o); if (lane >= o) x += y; }
    if (lane == 31) warp_tot[wid] = x;
    __syncthreads();
    if (wid == 0) {
        int t = warp_tot[lane];
        #pragma unroll
        for (int o = 1; o < 32; o <<= 1) { int y = __shfl_up_sync(~0u, t, o); if (lane >= o) t += y; }
        warp_tot[lane] = t;
    }
    __syncthreads();
    int excl = x - local + (wid > 0 ? warp_tot[wid - 1] : 0);
    g_offs[base]     = excl;
    g_offs[base + 1] = excl + v0;
    g_offs[base + 2] = excl + v0 + v1;
    g_offs[base + 3] = excl + v0 + v1 + v2;
}

__global__ void k_scatter(const float* __restrict__ anc) {
    int a = blockIdx.x * blockDim.x + threadIdx.x;
    if (a < NA) {
        int c = cell_of(__ldg((const float4*)anc + a));
        int p = atomicAdd(&g_cur[c], 1);
        g_sidx[g_offs[c] + p] = a;
    }
}

__global__ __launch_bounds__(TPB, 10) void rn_loss_kernel(
    const float* __restrict__ gt,     // (B, M, 5): cx, cy, w, h, label
    const float* __restrict__ pcls,   // (B, A, 1)
    const float* __restrict__ preg,   // (B, A, 4)
    const float* __restrict__ anc,    // (1, A, 4): x1, y1, x2, y2
    float* __restrict__ out)          // (2,)
{
    __shared__ float4 s_corn[NM];   // gt corners x1,y1,x2,y2
    __shared__ float  s_area[NM];   // gt area (corner-derived, matches ref rounding)
    __shared__ float4 s_raw[NM];    // gt cx,cy,w,h
    __shared__ float  s_c[TPB / 32], s_r[TPB / 32];
    __shared__ int    s_n[TPB / 32];

    const int img = blockIdx.y;
    const int tid = threadIdx.x;
    const int wid = tid >> 5, lid = tid & 31;
    const unsigned full = 0xFFFFFFFFu;

    float mylab = -1.0f;
    if (tid < NM) {
        const float* g = gt + (img * NM + tid) * 5;
        float cx = g[0], cy = g[1], w = g[2], h = g[3];
        mylab = g[4];
        float x1 = cx - 0.5f * w, y1 = cy - 0.5f * h;
        float x2 = cx + 0.5f * w, y2 = cy + 0.5f * h;
        s_corn[tid] = make_float4(x1, y1, x2, y2);
        s_area[tid] = (x2 - x1) * (y2 - y1);
        s_raw[tid]  = make_float4(cx, cy, w, h);
    }
    const int ngt = __syncthreads_count(tid < NM && mylab != -1.0f);

    const int sbase = blockIdx.x * SPAN + tid;   // slot in sorted order
    const int ibase = img * NA;

    int    ga[APT];                  // permuted (original) anchor index
    float4 A4[APT];
    float  Ca[APT];
    float  Ib[APT], Sb[APT];
    int    mb[APT];

    #pragma unroll
    for (int j = 0; j < APT; ++j) {
        int s = sbase + j * TPB;
        int ss = (s < NA) ? s : 0;            // tail: duplicate anchor, gated later
        ga[j] = __ldg(g_sidx + ss);
        A4[j] = __ldg((const float4*)anc + ga[j]);
        Ca[j] = (A4[j].z - A4[j].x) * (A4[j].w - A4[j].y);
        Ib[j] = 0.f; Sb[j] = 1.f; mb[j] = 0;
    }

    // warp bbox over (spatially sorted) anchors
    float wx1 = fminf(A4[0].x, A4[1].x);
    float wy1 = fminf(A4[0].y, A4[1].y);
    float wx2 = fmaxf(A4[0].z, A4[1].z);
    float wy2 = fmaxf(A4[0].w, A4[1].w);
    #pragma unroll
    for (int o = 16; o; o >>= 1) {
        wx1 = fminf(wx1, __shfl_xor_sync(full, wx1, o));
        wy1 = fminf(wy1, __shfl_xor_sync(full, wy1, o));
        wx2 = fmaxf(wx2, __shfl_xor_sync(full, wx2, o));
        wy2 = fmaxf(wy2, __shfl_xor_sync(full, wy2, o));
    }

    // warp-collective candidate mask: GTs whose bbox overlaps the warp bbox.
    // excluded GTs have I=0 vs every lane's anchor => cannot win the strict->
    // argmax (init (0,1)) nor affect iou_max thresholds => exact.
    unsigned long long cand;
    {
        bool ok0 = (lid < ngt);
        if (ok0) { float4 g = s_corn[lid];
                   ok0 = (g.x <= wx2) & (g.z >= wx1) & (g.y <= wy2) & (g.w >= wy1); }
        unsigned b0 = __ballot_sync(full, ok0);
        bool ok1 = (lid + 32 < ngt);
        if (ok1) { float4 g = s_corn[lid + 32];
                   ok1 = (g.x <= wx2) & (g.z >= wx1) & (g.y <= wy2) & (g.w >= wy1); }
        unsigned b1 = __ballot_sync(full, ok1);
        cand = ((unsigned long long)b1 << 32) | b0;
    }

    // masked scan, ascending m (preserves first-max tie-break)
    while (cand) {
        int m = __ffsll((long long)cand) - 1;
        cand &= cand - 1;
        const float4 gq = s_corn[m];
        const float  ar = s_area[m];
        #pragma unroll
        for (int j = 0; j < APT; ++j) {
            float w = fminf(A4[j].z, gq.z) - fmaxf(A4[j].x, gq.x);
            float h = fminf(A4[j].w, gq.w) - fmaxf(A4[j].y, gq.y);
            // one-clamp: any winner has I>0 => equals ref's clamped product
            float I = fmaxf(w, 0.f) * h;
            float S = Ca[j] + ar;
            bool  c = I * Sb[j] > Ib[j] * S;   // iou cross-mult compare
            Ib[j] = c ? I : Ib[j];
            Sb[j] = c ? S : Sb[j];
            mb[j] = c ? m : mb[j];
        }
    }

    float cterm = 0.f, rterm = 0.f;
    int   npos  = 0;

    #pragma unroll
    for (int j = 0; j < APT; ++j) {
        if (sbase + j * TPB >= NA) continue;
        const int a = ga[j];
        // iou_max >= 0.5 <=> 3*Ib >= Sb ;  iou_max < 0.4 <=> 7*Ib < 2*Sb
        const bool pos = (3.0f * Ib[j] >= Sb[j]);
        const bool neg = (7.0f * Ib[j] < 2.0f * Sb[j]);
        const float p = __ldg(pcls + ibase + a);

        if (pos) {
            npos += 1;
            // C == 1: every valid label is class 0 => one-hot target = 1
            float qq = 1.0f - p;
            cterm += 0.25f * qq * qq * (-__logf(p));

            const float aw  = A4[j].z - A4[j].x;
            const float ah  = A4[j].w - A4[j].y;
            const float acx = A4[j].x + 0.5f * aw;
            const float acy = A4[j].y + 0.5f * ah;
            const float4 gr = s_raw[mb[j]];
            const float gw = fmaxf(gr.z, 1.0f);
            const float gh = fmaxf(gr.w, 1.0f);
            const float t0 = ((gr.x - acx) / aw) / 0.1f;
            const float t1 = ((gr.y - acy) / ah) / 0.1f;
            const float t2 = logf(gw / aw) / 0.2f;   // rare path: keep precise
            const float t3 = logf(gh / ah) / 0.2f;

            const float4 rg = __ldg((const float4*)preg + ibase + a);
            const float d0 = fabsf(t0 - rg.x);
            const float d1 = fabsf(t1 - rg.y);
            const float d2 = fabsf(t2 - rg.z);
            const float d3 = fabsf(t3 - rg.w);
            const float TH = (float)(1.0 / 9.0);
            const float CC = (float)(0.5 / 9.0);
            rterm += (d0 <= TH) ? 4.5f * d0 * d0 : d0 - CC;
            rterm += (d1 <= TH) ? 4.5f * d1 * d1 : d1 - CC;
            rterm += (d2 <= TH) ? 4.5f * d2 * d2 : d2 - CC;
            rterm += (d3 <= TH) ? 4.5f * d3 * d3 : d3 - CC;
        } else if (neg) {
            cterm += 0.75f * p * p * (-__logf(1.0f - p));
        }
    }

    // reduction
    #pragma unroll
    for (int off = 16; off; off >>= 1) {
        cterm += __shfl_down_sync(full, cterm, off);
        rterm += __shfl_down_sync(full, rterm, off);
        npos  += __shfl_down_sync(full, npos, off);
    }
    if (lid == 0) { s_c[wid] = cterm; s_r[wid] = rterm; s_n[wid] = npos; }
    __syncthreads();

    if (tid == 0) {
        float c = 0.f, r = 0.f; int n = 0;
        #pragma unroll
        for (int i = 0; i < TPB / 32; ++i) { c += s_c[i]; r += s_r[i]; n += s_n[i]; }
        atomicAdd(&g_cls[img], c);
        atomicAdd(&g_reg[img], r);
        atomicAdd(&g_pos[img], n);

        __threadfence();
        unsigned v = atomicAdd(&g_ctr, 1u);
        if (v == (unsigned)(TOTAL_BLOCKS - 1)) {
            float cs = 0.f, rs = 0.f;
            #pragma unroll
            for (int i = 0; i < NB; ++i) {
                float cv = atomicAdd(&g_cls[i], 0.f);
                float rv = atomicAdd(&g_reg[i], 0.f);
                int   nv = atomicAdd(&g_pos[i], 0);
                float np = (float)nv;
                cs += cv / fmaxf(np, 1.0f);
                rs += (nv > 0) ? (rv / fmaxf(np * 4.0f, 1.0f)) : 0.0f;
            }
            out[0] = cs / (float)NB;
            out[1] = rs / (float)NB;
            #pragma unroll
            for (int i = 0; i < NB; ++i) { g_cls[i] = 0.f; g_reg[i] = 0.f; g_pos[i] = 0; }
            g_ctr = 0u;
        }
    }
}

extern "C" void kernel_launch(void* const* d_in, const int* in_sizes, int n_in,
                              void* d_out, int out_size) {
    const float* gt = (const float*)d_in[0];   // y_true_tmp (8,64,5)
    const float* pc = (const float*)d_in[1];   // y_classifs (8,120000,1)
    const float* pr = (const float*)d_in[2];   // y_regressions (8,120000,4)
    const float* an = (const float*)d_in[3];   // anchors (1,120000,4)

    k_zero<<<(NCELL + 255) / 256, 256>>>();
    k_hist<<<(NA + 255) / 256, 256>>>(an);
    k_scan<<<1, 1024>>>();
    k_scatter<<<(NA + 255) / 256, 256>>>(an);
    dim3 grid(GRIDX, NB);
    rn_loss_kernel<<<grid, TPB>>>(gt, pc, pr, an, (float*)d_out);
}